// round 10
// baseline (speedup 1.0000x reference)
#include <cuda_runtime.h>
#include <stdint.h>
#include <math.h>

#define B_   2
#define S_   1024
#define D_   1024
#define H_   16
#define DK_  64
#define DFF_ 2048
#define L_   4
#define BS_  (B_*S_)

// ---------------- scratch ----------------------------------------------------
__device__ float g_x[BS_*D_];
__device__ float g_q[BS_*D_];
__device__ float g_k[BS_*D_];
__device__ float g_v[BS_*D_];
__device__ float g_o[BS_*D_];
__device__ float g_h[BS_*DFF_];
__device__ float g_f[BS_*D_];

__device__ __forceinline__ float gelu_tanh_f(float x) {
    float x3 = x * x * x;
    return 0.5f * x * (1.0f + tanhf(0.7978845608028654f * (x + 0.044715f * x3)));
}

__device__ __forceinline__ uint32_t f2tf(float f) {
    uint32_t u;
    asm("cvt.rna.tf32.f32 %0, %1;" : "=r"(u) : "f"(f));
    return u;
}

__device__ __forceinline__ void mma_tf32(float* c, const uint32_t* a, const uint32_t* b) {
    asm volatile(
        "mma.sync.aligned.m16n8k8.row.col.f32.tf32.tf32.f32 "
        "{%0,%1,%2,%3}, {%4,%5,%6,%7}, {%8,%9}, {%0,%1,%2,%3};"
        : "+f"(c[0]), "+f"(c[1]), "+f"(c[2]), "+f"(c[3])
        : "r"(a[0]), "r"(a[1]), "r"(a[2]), "r"(a[3]), "r"(b[0]), "r"(b[1]));
}

__device__ __forceinline__ void cpa16(uint32_t saddr, const void* gptr) {
    asm volatile("cp.async.cg.shared.global [%0], [%1], 16;" :: "r"(saddr), "l"(gptr));
}
#define CP_COMMIT()  asm volatile("cp.async.commit_group;")
#define CP_WAIT(n)   asm volatile("cp.async.wait_group %0;" :: "n"(n))

// =============================================================================
// Pipelined GEMM: C[M,N] = A[M,K] @ W[K,N]. 128xTN tile, BK=32, 2-stage,
// 2 CTAs/SM. 8 warps (2M x 4N); warp tile 64 x (TN/4).
// EPI: 0 none, 1 +bias, 2 gelu(+bias). z selects fused QKV.
// =============================================================================
#define GA_STRIDE 36
#define GA_ELEMS  (128*GA_STRIDE)
#define GEMM_SMEM(TN) ((2*GA_ELEMS + 2*32*((TN)+4))*4)

template<int EPI, int TN>
__global__ __launch_bounds__(256, 2)
void gemm_pipe(const float* __restrict__ A,
               const float* __restrict__ W0, const float* __restrict__ W1,
               const float* __restrict__ W2, const float* __restrict__ bias,
               float* __restrict__ C0, float* __restrict__ C1, float* __restrict__ C2,
               int N, int K) {
    constexpr int BSTR = TN + 4;
    constexpr int GBE  = 32 * BSTR;
    constexpr int WN   = TN / 4;     // warp n width
    constexpr int NF   = TN / 32;    // 8-wide frags per warp
    constexpr int BCH  = TN / 4;     // b chunks per row
    constexpr int BPT  = TN / 32;    // b chunks per thread

    extern __shared__ float smem[];
    float* AsBase = smem;
    float* BsBase = smem + 2*GA_ELEMS;

    const float* W = (blockIdx.z == 0) ? W0 : (blockIdx.z == 1) ? W1 : W2;
    float*       C = (blockIdx.z == 0) ? C0 : (blockIdx.z == 1) ? C1 : C2;

    const int tid = threadIdx.x;
    const int row0 = blockIdx.y * 128, col0 = blockIdx.x * TN;
    const int w = tid >> 5, lane = tid & 31;
    const int wm = w >> 2, wn = w & 3;
    const int grp = lane >> 2, qd = lane & 3;
    const int nIter = K >> 5;

    uint32_t sA0 = (uint32_t)__cvta_generic_to_shared(AsBase);
    uint32_t sB0 = (uint32_t)__cvta_generic_to_shared(BsBase);

    #define LOAD_TILE(it, st) {                                                     \
        uint32_t sa = sA0 + (st)*GA_ELEMS*4;                                        \
        uint32_t sb = sB0 + (st)*GBE*4;                                             \
        int kt = (it) << 5;                                                         \
        _Pragma("unroll")                                                           \
        for (int i = 0; i < 4; i++) {                                               \
            int idx = tid + i * 256;                                                \
            int r = idx >> 3, c16 = idx & 7;                                        \
            cpa16(sa + (r*GA_STRIDE + c16*4)*4,                                     \
                  &A[(size_t)(row0 + r) * K + kt + c16*4]);                         \
        }                                                                           \
        _Pragma("unroll")                                                           \
        for (int i = 0; i < BPT; i++) {                                             \
            int idx = tid + i * 256;                                                \
            int r = idx / BCH, c4 = (idx % BCH) * 4;                                \
            cpa16(sb + (r*BSTR + c4)*4,                                             \
                  &W[(size_t)(kt + r) * N + col0 + c4]);                            \
        }                                                                           \
    }

    float acc[4][NF][4] = {};

    LOAD_TILE(0, 0); CP_COMMIT();

    for (int it = 0; it < nIter; it++) {
        CP_WAIT(0);
        __syncthreads();
        if (it + 1 < nIter) { LOAD_TILE(it + 1, (it + 1) & 1); CP_COMMIT(); }

        const float* As = AsBase + (it & 1) * GA_ELEMS;
        const float* Bs = BsBase + (it & 1) * GBE;
        #pragma unroll
        for (int kk = 0; kk < 4; kk++) {
            int kb = kk * 8;
            uint32_t af[4][4], bf[NF][2];
            #pragma unroll
            for (int mf = 0; mf < 4; mf++) {
                int r = wm * 64 + mf * 16 + grp;
                af[mf][0] = f2tf(As[r * GA_STRIDE + kb + qd]);
                af[mf][1] = f2tf(As[(r + 8) * GA_STRIDE + kb + qd]);
                af[mf][2] = f2tf(As[r * GA_STRIDE + kb + qd + 4]);
                af[mf][3] = f2tf(As[(r + 8) * GA_STRIDE + kb + qd + 4]);
            }
            #pragma unroll
            for (int nf = 0; nf < NF; nf++) {
                int c = wn * WN + nf * 8 + grp;
                bf[nf][0] = f2tf(Bs[(kb + qd) * BSTR + c]);
                bf[nf][1] = f2tf(Bs[(kb + qd + 4) * BSTR + c]);
            }
            #pragma unroll
            for (int mf = 0; mf < 4; mf++)
                #pragma unroll
                for (int nf = 0; nf < NF; nf++)
                    mma_tf32(acc[mf][nf], af[mf], bf[nf]);
        }
        __syncthreads();
    }
    #undef LOAD_TILE

    #pragma unroll
    for (int mf = 0; mf < 4; mf++) {
        int r = row0 + wm * 64 + mf * 16 + grp;
        #pragma unroll
        for (int nf = 0; nf < NF; nf++) {
            int c = col0 + wn * WN + nf * 8 + 2 * qd;
            float* a = acc[mf][nf];
            float v0 = a[0], v1 = a[1], v2 = a[2], v3 = a[3];
            if (EPI >= 1) {
                float b0 = bias[c], b1 = bias[c + 1];
                v0 += b0; v1 += b1; v2 += b0; v3 += b1;
            }
            if (EPI == 2) {
                v0 = gelu_tanh_f(v0); v1 = gelu_tanh_f(v1);
                v2 = gelu_tanh_f(v2); v3 = gelu_tanh_f(v3);
            }
            C[(size_t)r * N + c] = v0;       C[(size_t)r * N + c + 1] = v1;
            C[(size_t)(r + 8) * N + c] = v2; C[(size_t)(r + 8) * N + c + 1] = v3;
        }
    }
}

// =============================================================================
// Fused attention (R8 256-thread version): 32 q-rows per CTA of one (b,h).
// =============================================================================
#define FA_SSTRIDE 1028
#define FA_SBUF    (32*FA_SSTRIDE)
#define FA_QOFF    FA_SBUF
#define FA_KVOFF   (FA_SBUF + 32*68)
#define FA_KVBUF   (128*68)
#define FA_SMEM    ((FA_KVOFF + 2*FA_KVBUF)*4)

__global__ __launch_bounds__(256)
void fused_attn(const float* __restrict__ attn_bias, const int* __restrict__ mask,
                float* __restrict__ out) {
    extern __shared__ float smem[];
    float* sS  = smem;
    float* Qs  = smem + FA_QOFF;
    float* KVb = smem + FA_KVOFF;

    const int tid = threadIdx.x;
    const int w = tid >> 5, lane = tid & 31;
    const int wm = w >> 2, wn = w & 3;
    const int grp = lane >> 2, qd = lane & 3;
    const int row0 = blockIdx.x * 32;
    const int z = blockIdx.y, b = z >> 4, h = z & 15;

    const float* Qg = g_q + (size_t)b*S_*D_ + h*DK_;
    const float* Kg = g_k + (size_t)b*S_*D_ + h*DK_;
    const float* Vg = g_v + (size_t)b*S_*D_ + h*DK_;

    uint32_t sQ  = (uint32_t)__cvta_generic_to_shared(Qs);
    uint32_t sKV = (uint32_t)__cvta_generic_to_shared(KVb);

    #pragma unroll
    for (int i = 0; i < 2; i++) {
        int idx = tid + i*256;
        int r = idx >> 4, c = (idx & 15)*4;
        cpa16(sQ + (r*68 + c)*4, &Qg[(size_t)(row0+r)*D_ + c]);
    }
    #pragma unroll
    for (int i = 0; i < 8; i++) {
        int idx = tid + i*256;
        int r = idx >> 4, c = (idx & 15)*4;
        cpa16(sKV + (r*68 + c)*4, &Kg[(size_t)r*D_ + c]);
    }
    CP_COMMIT();

    // ---- phase 1: S = scale * Q K^T ----
    for (int t = 0; t < 8; t++) {
        __syncthreads();
        if (t + 1 < 8) {
            uint32_t dst = sKV + ((t+1)&1)*FA_KVBUF*4;
            int key0 = (t+1)*128;
            #pragma unroll
            for (int i = 0; i < 8; i++) {
                int idx = tid + i*256;
                int r = idx >> 4, c = (idx & 15)*4;
                cpa16(dst + (r*68 + c)*4, &Kg[(size_t)(key0+r)*D_ + c]);
            }
        }
        CP_COMMIT();
        CP_WAIT(1);
        __syncthreads();

        const float* Ks = KVb + (t&1)*FA_KVBUF;
        float acc[4][4] = {};
        #pragma unroll
        for (int kb8 = 0; kb8 < 8; kb8++) {
            int kb = kb8 * 8;
            uint32_t af[4], bf[4][2];
            int r = wm*16 + grp;
            af[0] = f2tf(Qs[r*68 + kb + qd]);
            af[1] = f2tf(Qs[(r+8)*68 + kb + qd]);
            af[2] = f2tf(Qs[r*68 + kb + qd + 4]);
            af[3] = f2tf(Qs[(r+8)*68 + kb + qd + 4]);
            #pragma unroll
            for (int nf = 0; nf < 4; nf++) {
                int c = wn*32 + nf*8 + grp;
                bf[nf][0] = f2tf(Ks[c*68 + kb + qd]);
                bf[nf][1] = f2tf(Ks[c*68 + kb + qd + 4]);
            }
            #pragma unroll
            for (int nf = 0; nf < 4; nf++)
                mma_tf32(acc[nf], af, bf[nf]);
        }
        {
            int r = wm*16 + grp;
            #pragma unroll
            for (int nf = 0; nf < 4; nf++) {
                int c = t*128 + wn*32 + nf*8 + 2*qd;
                sS[r*FA_SSTRIDE + c]       = acc[nf][0] * 0.125f;
                sS[r*FA_SSTRIDE + c + 1]   = acc[nf][1] * 0.125f;
                sS[(r+8)*FA_SSTRIDE + c]   = acc[nf][2] * 0.125f;
                sS[(r+8)*FA_SSTRIDE + c+1] = acc[nf][3] * 0.125f;
            }
        }
    }
    __syncthreads();

    // prefetch V tile 0 (overlaps softmax)
    #pragma unroll
    for (int i = 0; i < 8; i++) {
        int idx = tid + i*256;
        int r = idx >> 4, c = (idx & 15)*4;
        cpa16(sKV + (r*68 + c)*4, &Vg[(size_t)r*D_ + c]);
    }
    CP_COMMIT();

    // ---- phase 2: softmax, warp per row ----
    {
        const float* biasZ = attn_bias + (size_t)z*S_*S_;
        float* outZ = out + (size_t)z*S_*S_;
        const int* maskB = mask + b*S_;
        #pragma unroll
        for (int ri = 0; ri < 4; ri++) {
            int r = w*4 + ri;
            const float* bRow = biasZ + (size_t)(row0+r)*S_;
            float* oRow = outZ + (size_t)(row0+r)*S_;
            float* sRow = sS + r*FA_SSTRIDE;
            float4 vals[8];
            float m = -INFINITY;
            #pragma unroll
            for (int j = 0; j < 8; j++) {
                int c = lane*4 + j*128;
                float4 sv = *(float4*)&sRow[c];
                float4 bv = *(const float4*)&bRow[c];
                int4 mk = *(const int4*)&maskB[c];
                float4 v;
                v.x = mk.x ? sv.x + bv.x : -9e15f;
                v.y = mk.y ? sv.y + bv.y : -9e15f;
                v.z = mk.z ? sv.z + bv.z : -9e15f;
                v.w = mk.w ? sv.w + bv.w : -9e15f;
                vals[j] = v;
                m = fmaxf(m, fmaxf(fmaxf(v.x, v.y), fmaxf(v.z, v.w)));
            }
            #pragma unroll
            for (int o = 16; o > 0; o >>= 1) m = fmaxf(m, __shfl_xor_sync(~0u, m, o));
            float sum = 0.f;
            #pragma unroll
            for (int j = 0; j < 8; j++) {
                float4 v = vals[j];
                v.x = __expf(v.x - m); v.y = __expf(v.y - m);
                v.z = __expf(v.z - m); v.w = __expf(v.w - m);
                vals[j] = v;
                sum += v.x + v.y + v.z + v.w;
            }
            #pragma unroll
            for (int o = 16; o > 0; o >>= 1) sum += __shfl_xor_sync(~0u, sum, o);
            float inv = 1.0f / sum;
            #pragma unroll
            for (int j = 0; j < 8; j++) {
                int c = lane*4 + j*128;
                float4 v = vals[j];
                v.x *= inv; v.y *= inv; v.z *= inv; v.w *= inv;
                *(float4*)&sRow[c] = v;
                *(float4*)&oRow[c] = v;
            }
        }
    }

    // ---- phase 3: O = P @ V ----
    float accO[2][4] = {};
    for (int t = 0; t < 8; t++) {
        __syncthreads();
        if (t + 1 < 8) {
            uint32_t dst = sKV + ((t+1)&1)*FA_KVBUF*4;
            int key0 = (t+1)*128;
            #pragma unroll
            for (int i = 0; i < 8; i++) {
                int idx = tid + i*256;
                int r = idx >> 4, c = (idx & 15)*4;
                cpa16(dst + (r*68 + c)*4, &Vg[(size_t)(key0+r)*D_ + c]);
            }
        }
        CP_COMMIT();
        CP_WAIT(1);
        __syncthreads();

        const float* Vs = KVb + (t&1)*FA_KVBUF;
        #pragma unroll
        for (int kb8 = 0; kb8 < 16; kb8++) {
            int kcol = t*128 + kb8*8;
            uint32_t af[4];
            int r = wm*16 + grp;
            af[0] = f2tf(sS[r*FA_SSTRIDE + kcol + qd]);
            af[1] = f2tf(sS[(r+8)*FA_SSTRIDE + kcol + qd]);
            af[2] = f2tf(sS[r*FA_SSTRIDE + kcol + qd + 4]);
            af[3] = f2tf(sS[(r+8)*FA_SSTRIDE + kcol + qd + 4]);
            #pragma unroll
            for (int nf = 0; nf < 2; nf++) {
                int c = wn*16 + nf*8 + grp;
                uint32_t bf[2];
                bf[0] = f2tf(Vs[(kb8*8 + qd)*68 + c]);
                bf[1] = f2tf(Vs[(kb8*8 + qd + 4)*68 + c]);
                mma_tf32(accO[nf], af, bf);
            }
        }
    }
    {
        float* Og = g_o + (size_t)b*S_*D_ + h*DK_;
        int r = row0 + wm*16 + grp;
        #pragma unroll
        for (int nf = 0; nf < 2; nf++) {
            int c = wn*16 + nf*8 + 2*qd;
            Og[(size_t)r*D_ + c]       = accO[nf][0];
            Og[(size_t)r*D_ + c + 1]   = accO[nf][1];
            Og[(size_t)(r+8)*D_ + c]   = accO[nf][2];
            Og[(size_t)(r+8)*D_ + c+1] = accO[nf][3];
        }
    }
}

// ---------------- x = LayerNorm(x + r) * g + b, shuffle reduction -----------
__global__ void add_ln(float* __restrict__ x, const float* __restrict__ r,
                       const float* __restrict__ g, const float* __restrict__ bb) {
    float* row = x + (size_t)blockIdx.x * D_;
    const float* rr = r + (size_t)blockIdx.x * D_;
    __shared__ float red[8], red2[8];
    int t = threadIdx.x;
    int w = t >> 5, lane = t & 31;
    float v[4];
    float s = 0.f, s2 = 0.f;
    #pragma unroll
    for (int i = 0; i < 4; i++) {
        v[i] = row[t + i * 256] + rr[t + i * 256];
        s += v[i]; s2 += v[i] * v[i];
    }
    #pragma unroll
    for (int o = 16; o > 0; o >>= 1) {
        s  += __shfl_xor_sync(~0u, s, o);
        s2 += __shfl_xor_sync(~0u, s2, o);
    }
    if (lane == 0) { red[w] = s; red2[w] = s2; }
    __syncthreads();
    float ts = 0.f, ts2 = 0.f;
    #pragma unroll
    for (int i = 0; i < 8; i++) { ts += red[i]; ts2 += red2[i]; }
    float mu = ts * (1.0f / D_);
    float var = ts2 * (1.0f / D_) - mu * mu;
    float inv = rsqrtf(var + 1e-6f);
    #pragma unroll
    for (int i = 0; i < 4; i++) {
        int c = t + i * 256;
        row[c] = (v[i] - mu) * inv * g[c] + bb[c];
    }
}

__global__ void copyk(float* __restrict__ dst, const float* __restrict__ src, int n) {
    int i = blockIdx.x * 256 + threadIdx.x;
    if (i < n) dst[i] = src[i];
}

// ---------------------------------------------------------------------------
extern "C" void kernel_launch(void* const* d_in, const int* in_sizes, int n_in,
                              void* d_out, int out_size) {
    const float* x_in      = (const float*)d_in[0];
    const int*   mask      = (const int*)d_in[1];
    const float* attn_bias = (const float*)d_in[2];
    const float* Wq        = (const float*)d_in[3];
    const float* Wk        = (const float*)d_in[4];
    const float* Wv        = (const float*)d_in[5];
    const float* ln1_g     = (const float*)d_in[6];
    const float* ln1_b     = (const float*)d_in[7];
    const float* W1        = (const float*)d_in[8];
    const float* b1        = (const float*)d_in[9];
    const float* W2        = (const float*)d_in[10];
    const float* b2        = (const float*)d_in[11];
    const float* ln2_g     = (const float*)d_in[12];
    const float* ln2_b     = (const float*)d_in[13];
    float* out = (float*)d_out;

    cudaFuncSetAttribute((const void*)gemm_pipe<0,64>,  cudaFuncAttributeMaxDynamicSharedMemorySize, GEMM_SMEM(64));
    cudaFuncSetAttribute((const void*)gemm_pipe<2,128>, cudaFuncAttributeMaxDynamicSharedMemorySize, GEMM_SMEM(128));
    cudaFuncSetAttribute((const void*)gemm_pipe<1,64>,  cudaFuncAttributeMaxDynamicSharedMemorySize, GEMM_SMEM(64));
    cudaFuncSetAttribute((const void*)fused_attn,       cudaFuncAttributeMaxDynamicSharedMemorySize, FA_SMEM);

    float *px, *pq, *pk, *pv, *po, *ph, *pf;
    cudaGetSymbolAddress((void**)&px, g_x);
    cudaGetSymbolAddress((void**)&pq, g_q);
    cudaGetSymbolAddress((void**)&pk, g_k);
    cudaGetSymbolAddress((void**)&pv, g_v);
    cudaGetSymbolAddress((void**)&po, g_o);
    cudaGetSymbolAddress((void**)&ph, g_h);
    cudaGetSymbolAddress((void**)&pf, g_f);

    const int nX = BS_ * D_;
    copyk<<<(nX + 255) / 256, 256>>>(px, x_in, nX);

    dim3 gQKV(D_ / 64, BS_ / 128, 3);      // 16 x 16 x 3 = 768
    dim3 gFF1(DFF_ / 128, BS_ / 128, 1);   // 16 x 16 = 256
    dim3 gFF2(D_ / 64, BS_ / 128, 1);      // 16 x 16 = 256
    dim3 gFA(S_ / 32, B_ * H_);            // 32 x 32

    for (int n = 0; n < L_; n++) {
        const float* wq = Wq + (size_t)n * D_ * D_;
        const float* wk = Wk + (size_t)n * D_ * D_;
        const float* wv = Wv + (size_t)n * D_ * D_;
        float* scores = out + (size_t)n * B_ * H_ * S_ * S_;

        gemm_pipe<0,64><<<gQKV, 256, GEMM_SMEM(64)>>>(px, wq, wk, wv, nullptr,
                                                      pq, pk, pv, D_, D_);

        fused_attn<<<gFA, 256, FA_SMEM>>>(attn_bias, mask, scores);

        add_ln<<<BS_, 256>>>(px, po, ln1_g + n * D_, ln1_b + n * D_);

        const float* w1 = W1 + (size_t)n * D_ * DFF_;
        const float* w2 = W2 + (size_t)n * DFF_ * D_;
        gemm_pipe<2,128><<<gFF1, 256, GEMM_SMEM(128)>>>(px, w1, w1, w1, b1 + n * DFF_,
                                                        ph, ph, ph, DFF_, D_);
        gemm_pipe<1,64><<<gFF2, 256, GEMM_SMEM(64)>>>(ph, w2, w2, w2, b2 + n * D_,
                                                      pf, pf, pf, D_, DFF_);

        add_ln<<<BS_, 256>>>(px, pf, ln2_g + n * D_, ln2_b + n * D_);
    }

    copyk<<<(nX + 255) / 256, 256>>>(out + (size_t)L_ * B_ * H_ * S_ * S_, px, nX);
}

// round 12
// speedup vs baseline: 1.4878x; 1.4878x over previous
#include <cuda_runtime.h>
#include <cuda_fp16.h>
#include <stdint.h>
#include <math.h>

#define B_   2
#define S_   1024
#define D_   1024
#define H_   16
#define DK_  64
#define DFF_ 2048
#define L_   4
#define BS_  (B_*S_)

extern __shared__ char dsmem[];

// ---------------- scratch ----------------------------------------------------
__device__ float  g_x[BS_*D_];
__device__ float  g_o[BS_*D_];
__device__ float  g_f[BS_*D_];
__device__ __half g_xh[BS_*D_];
__device__ __half g_qh[BS_*D_];
__device__ __half g_kh[BS_*D_];
__device__ __half g_vh[BS_*D_];
__device__ __half g_hh[BS_*DFF_];
// fp16 weights, TRANSPOSED to [N][K]
__device__ __half g_wqkvh[L_*3*D_*D_];
__device__ __half g_w1h[L_*DFF_*D_];
__device__ __half g_w2h[L_*D_*DFF_];

__device__ __forceinline__ float gelu_tanh_f(float x) {
    float x3 = x * x * x;
    return 0.5f * x * (1.0f + tanhf(0.7978845608028654f * (x + 0.044715f * x3)));
}

__device__ __forceinline__ void mma_f16(float* c, const uint32_t* a, const uint32_t* b) {
    asm volatile(
        "mma.sync.aligned.m16n8k16.row.col.f32.f16.f16.f32 "
        "{%0,%1,%2,%3}, {%4,%5,%6,%7}, {%8,%9}, {%0,%1,%2,%3};"
        : "+f"(c[0]), "+f"(c[1]), "+f"(c[2]), "+f"(c[3])
        : "r"(a[0]), "r"(a[1]), "r"(a[2]), "r"(a[3]), "r"(b[0]), "r"(b[1]));
}

__device__ __forceinline__ uint32_t packf2(float lo, float hi) {
    __half2 h = __floats2half2_rn(lo, hi);
    return *(uint32_t*)&h;
}
__device__ __forceinline__ uint32_t packh2(__half lo, __half hi) {
    __half2 h = __halves2half2(lo, hi);
    return *(uint32_t*)&h;
}

__device__ __forceinline__ void cpa16(uint32_t saddr, const void* gptr) {
    asm volatile("cp.async.cg.shared.global [%0], [%1], 16;" :: "r"(saddr), "l"(gptr));
}
#define CP_COMMIT()  asm volatile("cp.async.commit_group;")
#define CP_WAIT(n)   asm volatile("cp.async.wait_group %0;" :: "n"(n))

// =============================================================================
// fp16 GEMM: C[M,N] = A[M,K] @ W^T (W stored [N][K] fp16). 128x128 tile,
// BK=32, 3-stage cp.async, 2 CTAs/SM, 8 warps (2Mx4N), mma m16n8k16.
// smem/stage: A 128x(32+8) halfs + B same = 20480B. 3 stages.
// EPI 0: half2 out (q/k/v by z). EPI 1: +bias -> f32. EPI 2: gelu+bias -> half.
// =============================================================================
#define AH_STR  40
#define A_ELE   (128*AH_STR)
#define ST_ELE  (2*A_ELE)
#define GEMM_SMEM (3*ST_ELE*2)

template<int EPI>
__global__ __launch_bounds__(256, 2)
void gemm_pipe(const __half* __restrict__ A,
               const __half* __restrict__ W0, const __half* __restrict__ W1,
               const __half* __restrict__ W2, const float* __restrict__ bias,
               float* __restrict__ Cf,
               __half* __restrict__ C0, __half* __restrict__ C1,
               __half* __restrict__ C2,
               int N, int K) {
    const __half* W = (blockIdx.z == 0) ? W0 : (blockIdx.z == 1) ? W1 : W2;
    __half* Ch = (blockIdx.z == 0) ? C0 : (blockIdx.z == 1) ? C1 : C2;

    const int tid = threadIdx.x;
    const int row0 = blockIdx.y * 128, col0 = blockIdx.x * 128;
    const int w = tid >> 5, lane = tid & 31;
    const int wm = w >> 2, wn = w & 3;
    const int grp = lane >> 2, qd = lane & 3;
    const int nIter = K >> 5;

    uint32_t sBase = (uint32_t)__cvta_generic_to_shared(dsmem);

    #define LOAD_TILE(it, st) {                                                     \
        uint32_t sa = sBase + (st)*ST_ELE*2;                                        \
        uint32_t sb = sa + A_ELE*2;                                                 \
        int kt = (it) << 5;                                                         \
        _Pragma("unroll")                                                           \
        for (int i = 0; i < 2; i++) {                                               \
            int idx = tid + i * 256;                                                \
            int r = idx >> 2, ch = idx & 3;                                         \
            cpa16(sa + r*80 + ch*16, &A[(size_t)(row0 + r) * K + kt + ch*8]);       \
        }                                                                           \
        _Pragma("unroll")                                                           \
        for (int i = 0; i < 2; i++) {                                               \
            int idx = tid + i * 256;                                                \
            int r = idx >> 2, ch = idx & 3;                                         \
            cpa16(sb + r*80 + ch*16, &W[(size_t)(col0 + r) * K + kt + ch*8]);       \
        }                                                                           \
    }

    float acc[4][4][4] = {};

    LOAD_TILE(0, 0); CP_COMMIT();
    LOAD_TILE(1, 1); CP_COMMIT();

    for (int it = 0; it < nIter; it++) {
        CP_WAIT(1);
        __syncthreads();
        if (it + 2 < nIter) { LOAD_TILE(it + 2, (it + 2) % 3); }
        CP_COMMIT();

        const uint32_t* S32 = (const uint32_t*)(dsmem + (it % 3)*ST_ELE*2);
        const uint32_t* A32 = S32;
        const uint32_t* B32 = S32 + A_ELE/2;
        #pragma unroll
        for (int kk = 0; kk < 2; kk++) {
            int kb2 = kk * 8;
            uint32_t af[4][4], bf[4][2];
            #pragma unroll
            for (int mf = 0; mf < 4; mf++) {
                int r = wm * 64 + mf * 16 + grp;
                af[mf][0] = A32[r * 20 + kb2 + qd];
                af[mf][1] = A32[(r + 8) * 20 + kb2 + qd];
                af[mf][2] = A32[r * 20 + kb2 + qd + 4];
                af[mf][3] = A32[(r + 8) * 20 + kb2 + qd + 4];
            }
            #pragma unroll
            for (int nf = 0; nf < 4; nf++) {
                int c = wn * 32 + nf * 8 + grp;
                bf[nf][0] = B32[c * 20 + kb2 + qd];
                bf[nf][1] = B32[c * 20 + kb2 + qd + 4];
            }
            #pragma unroll
            for (int mf = 0; mf < 4; mf++)
                #pragma unroll
                for (int nf = 0; nf < 4; nf++)
                    mma_f16(acc[mf][nf], af[mf], bf[nf]);
        }
        __syncthreads();
    }
    #undef LOAD_TILE

    #pragma unroll
    for (int mf = 0; mf < 4; mf++) {
        int r = row0 + wm * 64 + mf * 16 + grp;
        #pragma unroll
        for (int nf = 0; nf < 4; nf++) {
            int c = col0 + wn * 32 + nf * 8 + 2 * qd;
            float* a = acc[mf][nf];
            float v0 = a[0], v1 = a[1], v2 = a[2], v3 = a[3];
            if (EPI >= 1) {
                float b0 = bias[c], b1 = bias[c + 1];
                v0 += b0; v1 += b1; v2 += b0; v3 += b1;
            }
            if (EPI == 2) {
                v0 = gelu_tanh_f(v0); v1 = gelu_tanh_f(v1);
                v2 = gelu_tanh_f(v2); v3 = gelu_tanh_f(v3);
            }
            if (EPI == 1) {
                Cf[(size_t)r * N + c] = v0;       Cf[(size_t)r * N + c + 1] = v1;
                Cf[(size_t)(r + 8) * N + c] = v2; Cf[(size_t)(r + 8) * N + c + 1] = v3;
            } else {
                *(__half2*)&Ch[(size_t)r * N + c]       = __floats2half2_rn(v0, v1);
                *(__half2*)&Ch[(size_t)(r + 8) * N + c] = __floats2half2_rn(v2, v3);
            }
        }
    }
}

// =============================================================================
// Fused attention: 256 thr, 32 q-rows per CTA of one (b,h). fp16 Q/K/V.
// Rows are FULL DK=64 halfs + 8 pad = 72-half stride (36 u32, 144 B).
// smem: sS f32[32][1028] | Qs half[32][72] | KV half[2][128][72]
// =============================================================================
#define FA_SSTRIDE 1028
#define FA_SS_BYTES (32*FA_SSTRIDE*4)
#define FA_HSTR     72
#define FA_Q_BYTES  (32*FA_HSTR*2)
#define FA_KV_BYTES (128*FA_HSTR*2)
#define FA_SMEM     (FA_SS_BYTES + FA_Q_BYTES + 2*FA_KV_BYTES)

__global__ __launch_bounds__(256)
void fused_attn(const float* __restrict__ attn_bias, const int* __restrict__ mask,
                float* __restrict__ out) {
    float* sS = (float*)dsmem;
    char*  qBase  = dsmem + FA_SS_BYTES;
    char*  kvBase = qBase + FA_Q_BYTES;

    const int tid = threadIdx.x;
    const int w = tid >> 5, lane = tid & 31;
    const int wm = w >> 2, wn = w & 3;
    const int grp = lane >> 2, qd = lane & 3;
    const int row0 = blockIdx.x * 32;
    const int z = blockIdx.y, b = z >> 4, h = z & 15;

    const __half* Qg = g_qh + (size_t)b*S_*D_ + h*DK_;
    const __half* Kg = g_kh + (size_t)b*S_*D_ + h*DK_;
    const __half* Vg = g_vh + (size_t)b*S_*D_ + h*DK_;

    uint32_t sQ  = (uint32_t)__cvta_generic_to_shared(qBase);
    uint32_t sKV = (uint32_t)__cvta_generic_to_shared(kvBase);

    // preload Q (32 rows x 8 chunks = 256) + K tile 0 (128 x 8 = 1024)
    {
        int r = tid >> 3, ch = tid & 7;
        cpa16(sQ + r*144 + ch*16, &Qg[(size_t)(row0+r)*D_ + ch*8]);
    }
    #pragma unroll
    for (int i = 0; i < 4; i++) {
        int idx = tid + i*256;
        int r = idx >> 3, ch = idx & 7;
        cpa16(sKV + r*144 + ch*16, &Kg[(size_t)r*D_ + ch*8]);
    }
    CP_COMMIT();

    // ---- phase 1: S = scale * Q K^T  (8 key tiles of 128) ----
    for (int t = 0; t < 8; t++) {
        __syncthreads();
        if (t + 1 < 8) {
            uint32_t dst = sKV + ((t+1)&1)*FA_KV_BYTES;
            int key0 = (t+1)*128;
            #pragma unroll
            for (int i = 0; i < 4; i++) {
                int idx = tid + i*256;
                int r = idx >> 3, ch = idx & 7;
                cpa16(dst + r*144 + ch*16, &Kg[(size_t)(key0+r)*D_ + ch*8]);
            }
        }
        CP_COMMIT();
        CP_WAIT(1);
        __syncthreads();

        const uint32_t* Q32 = (const uint32_t*)qBase;
        const uint32_t* K32 = (const uint32_t*)(kvBase + (t&1)*FA_KV_BYTES);
        float acc[4][4] = {};
        #pragma unroll
        for (int kk = 0; kk < 4; kk++) {
            int kb2 = kk * 8;
            uint32_t af[4], bf[4][2];
            int r = wm*16 + grp;
            af[0] = Q32[r*36 + kb2 + qd];
            af[1] = Q32[(r+8)*36 + kb2 + qd];
            af[2] = Q32[r*36 + kb2 + qd + 4];
            af[3] = Q32[(r+8)*36 + kb2 + qd + 4];
            #pragma unroll
            for (int nf = 0; nf < 4; nf++) {
                int c = wn*32 + nf*8 + grp;
                bf[nf][0] = K32[c*36 + kb2 + qd];
                bf[nf][1] = K32[c*36 + kb2 + qd + 4];
            }
            #pragma unroll
            for (int nf = 0; nf < 4; nf++)
                mma_f16(acc[nf], af, bf[nf]);
        }
        {
            int r = wm*16 + grp;
            #pragma unroll
            for (int nf = 0; nf < 4; nf++) {
                int c = t*128 + wn*32 + nf*8 + 2*qd;
                sS[r*FA_SSTRIDE + c]       = acc[nf][0] * 0.125f;
                sS[r*FA_SSTRIDE + c + 1]   = acc[nf][1] * 0.125f;
                sS[(r+8)*FA_SSTRIDE + c]   = acc[nf][2] * 0.125f;
                sS[(r+8)*FA_SSTRIDE + c+1] = acc[nf][3] * 0.125f;
            }
        }
    }
    __syncthreads();

    // prefetch V tile 0 (overlaps softmax)
    #pragma unroll
    for (int i = 0; i < 4; i++) {
        int idx = tid + i*256;
        int r = idx >> 3, ch = idx & 7;
        cpa16(sKV + r*144 + ch*16, &Vg[(size_t)r*D_ + ch*8]);
    }
    CP_COMMIT();

    // ---- phase 2: softmax, warp per row ----
    {
        const float* biasZ = attn_bias + (size_t)z*S_*S_;
        float* outZ = out + (size_t)z*S_*S_;
        const int* maskB = mask + b*S_;
        #pragma unroll
        for (int ri = 0; ri < 4; ri++) {
            int r = w*4 + ri;
            const float* bRow = biasZ + (size_t)(row0+r)*S_;
            float* oRow = outZ + (size_t)(row0+r)*S_;
            float* sRow = sS + r*FA_SSTRIDE;
            float4 vals[8];
            float m = -INFINITY;
            #pragma unroll
            for (int j = 0; j < 8; j++) {
                int c = lane*4 + j*128;
                float4 sv = *(float4*)&sRow[c];
                float4 bv = *(const float4*)&bRow[c];
                int4 mk = *(const int4*)&maskB[c];
                float4 v;
                v.x = mk.x ? sv.x + bv.x : -9e15f;
                v.y = mk.y ? sv.y + bv.y : -9e15f;
                v.z = mk.z ? sv.z + bv.z : -9e15f;
                v.w = mk.w ? sv.w + bv.w : -9e15f;
                vals[j] = v;
                m = fmaxf(m, fmaxf(fmaxf(v.x, v.y), fmaxf(v.z, v.w)));
            }
            #pragma unroll
            for (int o = 16; o > 0; o >>= 1) m = fmaxf(m, __shfl_xor_sync(~0u, m, o));
            float sum = 0.f;
            #pragma unroll
            for (int j = 0; j < 8; j++) {
                float4 v = vals[j];
                v.x = __expf(v.x - m); v.y = __expf(v.y - m);
                v.z = __expf(v.z - m); v.w = __expf(v.w - m);
                vals[j] = v;
                sum += v.x + v.y + v.z + v.w;
            }
            #pragma unroll
            for (int o = 16; o > 0; o >>= 1) sum += __shfl_xor_sync(~0u, sum, o);
            float inv = 1.0f / sum;
            #pragma unroll
            for (int j = 0; j < 8; j++) {
                int c = lane*4 + j*128;
                float4 v = vals[j];
                v.x *= inv; v.y *= inv; v.z *= inv; v.w *= inv;
                *(float4*)&sRow[c] = v;
                *(float4*)&oRow[c] = v;
            }
        }
    }

    // ---- phase 3: O = P @ V  (8 value tiles of 128) ----
    float accO[2][4] = {};
    for (int t = 0; t < 8; t++) {
        __syncthreads();
        if (t + 1 < 8) {
            uint32_t dst = sKV + ((t+1)&1)*FA_KV_BYTES;
            int key0 = (t+1)*128;
            #pragma unroll
            for (int i = 0; i < 4; i++) {
                int idx = tid + i*256;
                int r = idx >> 3, ch = idx & 7;
                cpa16(dst + r*144 + ch*16, &Vg[(size_t)(key0+r)*D_ + ch*8]);
            }
        }
        CP_COMMIT();
        CP_WAIT(1);
        __syncthreads();

        const __half* Vs = (const __half*)(kvBase + (t&1)*FA_KV_BYTES);
        #pragma unroll
        for (int kk = 0; kk < 8; kk++) {
            int kl = kk * 16;
            int kg = t*128 + kl;
            uint32_t af[4];
            int r = wm*16 + grp;
            af[0] = packf2(sS[r*FA_SSTRIDE + kg + 2*qd],     sS[r*FA_SSTRIDE + kg + 2*qd + 1]);
            af[1] = packf2(sS[(r+8)*FA_SSTRIDE + kg + 2*qd], sS[(r+8)*FA_SSTRIDE + kg + 2*qd + 1]);
            af[2] = packf2(sS[r*FA_SSTRIDE + kg + 2*qd + 8], sS[r*FA_SSTRIDE + kg + 2*qd + 9]);
            af[3] = packf2(sS[(r+8)*FA_SSTRIDE + kg + 2*qd + 8], sS[(r+8)*FA_SSTRIDE + kg + 2*qd + 9]);
            #pragma unroll
            for (int nf = 0; nf < 2; nf++) {
                int c = wn*16 + nf*8 + grp;
                uint32_t bf[2];
                bf[0] = packh2(Vs[(kl + 2*qd)*FA_HSTR + c],     Vs[(kl + 2*qd + 1)*FA_HSTR + c]);
                bf[1] = packh2(Vs[(kl + 2*qd + 8)*FA_HSTR + c], Vs[(kl + 2*qd + 9)*FA_HSTR + c]);
                mma_f16(accO[nf], af, bf);
            }
        }
    }
    {
        float* Og = g_o + (size_t)b*S_*D_ + h*DK_;
        int r = row0 + wm*16 + grp;
        #pragma unroll
        for (int nf = 0; nf < 2; nf++) {
            int c = wn*16 + nf*8 + 2*qd;
            Og[(size_t)r*D_ + c]       = accO[nf][0];
            Og[(size_t)r*D_ + c + 1]   = accO[nf][1];
            Og[(size_t)(r+8)*D_ + c]   = accO[nf][2];
            Og[(size_t)(r+8)*D_ + c+1] = accO[nf][3];
        }
    }
}

// ---------------- x = LayerNorm(x + r) * g + b, shuffle reduction, +fp16 ----
__global__ void add_ln(float* __restrict__ x, const float* __restrict__ r,
                       const float* __restrict__ g, const float* __restrict__ bb,
                       __half* __restrict__ xh) {
    float* row = x + (size_t)blockIdx.x * D_;
    const float* rr = r + (size_t)blockIdx.x * D_;
    __half* hrow = xh + (size_t)blockIdx.x * D_;
    __shared__ float red[8], red2[8];
    int t = threadIdx.x;
    int w = t >> 5, lane = t & 31;
    float v[4];
    float s = 0.f, s2 = 0.f;
    #pragma unroll
    for (int i = 0; i < 4; i++) {
        v[i] = row[t + i * 256] + rr[t + i * 256];
        s += v[i]; s2 += v[i] * v[i];
    }
    #pragma unroll
    for (int o = 16; o > 0; o >>= 1) {
        s  += __shfl_xor_sync(~0u, s, o);
        s2 += __shfl_xor_sync(~0u, s2, o);
    }
    if (lane == 0) { red[w] = s; red2[w] = s2; }
    __syncthreads();
    float ts = 0.f, ts2 = 0.f;
    #pragma unroll
    for (int i = 0; i < 8; i++) { ts += red[i]; ts2 += red2[i]; }
    float mu = ts * (1.0f / D_);
    float var = ts2 * (1.0f / D_) - mu * mu;
    float inv = rsqrtf(var + 1e-6f);
    #pragma unroll
    for (int i = 0; i < 4; i++) {
        int c = t + i * 256;
        float o = (v[i] - mu) * inv * g[c] + bb[c];
        row[c] = o;
        hrow[c] = __float2half(o);
    }
}

// ---------------- weight prep: W[K][N] f32 -> WT[N][K] fp16 -----------------
__global__ void wt_prep(const float* __restrict__ Wq, const float* __restrict__ Wk,
                        const float* __restrict__ Wv, const float* __restrict__ W1,
                        const float* __restrict__ W2) {
    int z = blockIdx.z;
    const float* src; __half* dst; int K, N;
    if (z < 12) {
        int l = z / 3, which = z % 3;
        const float* base = (which == 0) ? Wq : (which == 1) ? Wk : Wv;
        src = base + (size_t)l * D_ * D_;
        dst = g_wqkvh + (size_t)z * D_ * D_;
        K = D_; N = D_;
    } else if (z < 16) {
        int l = z - 12;
        src = W1 + (size_t)l * D_ * DFF_;
        dst = g_w1h + (size_t)l * DFF_ * D_;
        K = D_; N = DFF_;
    } else {
        int l = z - 16;
        src = W2 + (size_t)l * DFF_ * D_;
        dst = g_w2h + (size_t)l * D_ * DFF_;
        K = DFF_; N = D_;
    }
    int n0 = blockIdx.x * 32, k0 = blockIdx.y * 32;
    if (n0 >= N || k0 >= K) return;
    __shared__ float tile[32][33];
    int tid = threadIdx.x;
    #pragma unroll
    for (int i = 0; i < 4; i++) {
        int idx = tid + i * 256;
        int kr = idx >> 5, nc = idx & 31;
        tile[kr][nc] = src[(size_t)(k0 + kr) * N + n0 + nc];
    }
    __syncthreads();
    #pragma unroll
    for (int i = 0; i < 4; i++) {
        int idx = tid + i * 256;
        int nr = idx >> 5, kc = idx & 31;
        dst[(size_t)(n0 + nr) * K + k0 + kc] = __float2half(tile[kc][nr]);
    }
}

// ---------------- helpers ----------------------------------------------------
__global__ void split_copy(float* __restrict__ dst, __half* __restrict__ dsth,
                           const float* __restrict__ src) {
    int i = (blockIdx.x * 256 + threadIdx.x) * 4;
    float4 v = *(const float4*)&src[i];
    *(float4*)&dst[i] = v;
    *(__half2*)&dsth[i]     = __floats2half2_rn(v.x, v.y);
    *(__half2*)&dsth[i + 2] = __floats2half2_rn(v.z, v.w);
}

__global__ void copyk(float* __restrict__ dst, const float* __restrict__ src, int n) {
    int i = blockIdx.x * 256 + threadIdx.x;
    if (i < n) dst[i] = src[i];
}

// ---------------------------------------------------------------------------
extern "C" void kernel_launch(void* const* d_in, const int* in_sizes, int n_in,
                              void* d_out, int out_size) {
    const float* x_in      = (const float*)d_in[0];
    const int*   mask      = (const int*)d_in[1];
    const float* attn_bias = (const float*)d_in[2];
    const float* Wq        = (const float*)d_in[3];
    const float* Wk        = (const float*)d_in[4];
    const float* Wv        = (const float*)d_in[5];
    const float* ln1_g     = (const float*)d_in[6];
    const float* ln1_b     = (const float*)d_in[7];
    const float* W1        = (const float*)d_in[8];
    const float* b1        = (const float*)d_in[9];
    const float* W2        = (const float*)d_in[10];
    const float* b2        = (const float*)d_in[11];
    const float* ln2_g     = (const float*)d_in[12];
    const float* ln2_b     = (const float*)d_in[13];
    float* out = (float*)d_out;

    cudaFuncSetAttribute(gemm_pipe<0>, cudaFuncAttributeMaxDynamicSharedMemorySize, GEMM_SMEM);
    cudaFuncSetAttribute(gemm_pipe<1>, cudaFuncAttributeMaxDynamicSharedMemorySize, GEMM_SMEM);
    cudaFuncSetAttribute(gemm_pipe<2>, cudaFuncAttributeMaxDynamicSharedMemorySize, GEMM_SMEM);
    cudaFuncSetAttribute(fused_attn,   cudaFuncAttributeMaxDynamicSharedMemorySize, FA_SMEM);

    float *px, *po, *pf;
    __half *pxh, *pqh, *pkh, *pvh, *phh, *pwqkvh, *pw1h, *pw2h;
    cudaGetSymbolAddress((void**)&px, g_x);
    cudaGetSymbolAddress((void**)&po, g_o);
    cudaGetSymbolAddress((void**)&pf, g_f);
    cudaGetSymbolAddress((void**)&pxh, g_xh);
    cudaGetSymbolAddress((void**)&pqh, g_qh);
    cudaGetSymbolAddress((void**)&pkh, g_kh);
    cudaGetSymbolAddress((void**)&pvh, g_vh);
    cudaGetSymbolAddress((void**)&phh, g_hh);
    cudaGetSymbolAddress((void**)&pwqkvh, g_wqkvh);
    cudaGetSymbolAddress((void**)&pw1h, g_w1h);
    cudaGetSymbolAddress((void**)&pw2h, g_w2h);

    const int nX = BS_ * D_;

    wt_prep<<<dim3(64, 64, 20), 256>>>(Wq, Wk, Wv, W1, W2);
    split_copy<<<nX / 1024, 256>>>(px, pxh, x_in);

    dim3 gQKV(D_ / 128, BS_ / 128, 3);     // 8 x 16 x 3
    dim3 gFF1(DFF_ / 128, BS_ / 128, 1);   // 16 x 16
    dim3 gFF2(D_ / 128, BS_ / 128, 1);     // 8 x 16
    dim3 gFA(S_ / 32, B_ * H_);            // 32 x 32

    for (int n = 0; n < L_; n++) {
        float* scores = out + (size_t)n * B_ * H_ * S_ * S_;
        const __half* wqkv = pwqkvh + (size_t)n * 3 * D_ * D_;

        gemm_pipe<0><<<gQKV, 256, GEMM_SMEM>>>(
            pxh, wqkv, wqkv + (size_t)D_ * D_, wqkv + (size_t)2 * D_ * D_,
            nullptr, nullptr, pqh, pkh, pvh, D_, D_);

        fused_attn<<<gFA, 256, FA_SMEM>>>(attn_bias, mask, scores);

        add_ln<<<BS_, 256>>>(px, po, ln1_g + n * D_, ln1_b + n * D_, pxh);

        gemm_pipe<2><<<gFF1, 256, GEMM_SMEM>>>(
            pxh, pw1h + (size_t)n * DFF_ * D_, pw1h + (size_t)n * DFF_ * D_,
            pw1h + (size_t)n * DFF_ * D_, b1 + n * DFF_,
            nullptr, phh, phh, phh, DFF_, D_);

        gemm_pipe<1><<<gFF2, 256, GEMM_SMEM>>>(
            phh, pw2h + (size_t)n * D_ * DFF_, pw2h + (size_t)n * D_ * DFF_,
            pw2h + (size_t)n * D_ * DFF_, b2 + n * D_,
            pf, nullptr, nullptr, nullptr, D_, DFF_);

        add_ln<<<BS_, 256>>>(px, pf, ln2_g + n * D_, ln2_b + n * D_, pxh);
    }

    copyk<<<(nX + 255) / 256, 256>>>(out + (size_t)L_ * B_ * H_ * S_ * S_, px, nX);
}

// round 15
// speedup vs baseline: 1.8485x; 1.2424x over previous
#include <cuda_runtime.h>
#include <cuda_fp16.h>
#include <stdint.h>
#include <math.h>

#define B_   2
#define S_   1024
#define D_   1024
#define H_   16
#define DK_  64
#define DFF_ 2048
#define L_   4
#define BS_  (B_*S_)

extern __shared__ char dsmem[];

// ---------------- scratch ----------------------------------------------------
__device__ float  g_x[BS_*D_];
__device__ float  g_o[BS_*D_];
__device__ float  g_f[BS_*D_];
__device__ __half g_xh[BS_*D_];
__device__ __half g_qh[BS_*D_];
__device__ __half g_kh[BS_*D_];
__device__ __half g_vh[BS_*D_];
__device__ __half g_hh[BS_*DFF_];
// fp16 weights, TRANSPOSED to [N][K]
__device__ __half g_wqkvh[L_*3*D_*D_];
__device__ __half g_w1h[L_*DFF_*D_];
__device__ __half g_w2h[L_*D_*DFF_];

__device__ __forceinline__ float gelu_tanh_f(float x) {
    float x3 = x * x * x;
    return 0.5f * x * (1.0f + tanhf(0.7978845608028654f * (x + 0.044715f * x3)));
}

__device__ __forceinline__ void mma_f16(float* c, const uint32_t* a, const uint32_t* b) {
    asm volatile(
        "mma.sync.aligned.m16n8k16.row.col.f32.f16.f16.f32 "
        "{%0,%1,%2,%3}, {%4,%5,%6,%7}, {%8,%9}, {%0,%1,%2,%3};"
        : "+f"(c[0]), "+f"(c[1]), "+f"(c[2]), "+f"(c[3])
        : "r"(a[0]), "r"(a[1]), "r"(a[2]), "r"(a[3]), "r"(b[0]), "r"(b[1]));
}

__device__ __forceinline__ uint32_t packh2(__half lo, __half hi) {
    __half2 h = __halves2half2(lo, hi);
    return *(uint32_t*)&h;
}

__device__ __forceinline__ void cpa16(uint32_t saddr, const void* gptr) {
    asm volatile("cp.async.cg.shared.global [%0], [%1], 16;" :: "r"(saddr), "l"(gptr));
}
#define CP_COMMIT()  asm volatile("cp.async.commit_group;")
#define CP_WAIT(n)   asm volatile("cp.async.wait_group %0;" :: "n"(n))

// =============================================================================
// fp16 GEMM (unchanged from R12): 128x128, BK=32, 3-stage, 2 CTAs/SM.
// =============================================================================
#define AH_STR  40
#define A_ELE   (128*AH_STR)
#define ST_ELE  (2*A_ELE)
#define GEMM_SMEM (3*ST_ELE*2)

template<int EPI>
__global__ __launch_bounds__(256, 2)
void gemm_pipe(const __half* __restrict__ A,
               const __half* __restrict__ W0, const __half* __restrict__ W1,
               const __half* __restrict__ W2, const float* __restrict__ bias,
               float* __restrict__ Cf,
               __half* __restrict__ C0, __half* __restrict__ C1,
               __half* __restrict__ C2,
               int N, int K) {
    const __half* W = (blockIdx.z == 0) ? W0 : (blockIdx.z == 1) ? W1 : W2;
    __half* Ch = (blockIdx.z == 0) ? C0 : (blockIdx.z == 1) ? C1 : C2;

    const int tid = threadIdx.x;
    const int row0 = blockIdx.y * 128, col0 = blockIdx.x * 128;
    const int w = tid >> 5, lane = tid & 31;
    const int wm = w >> 2, wn = w & 3;
    const int grp = lane >> 2, qd = lane & 3;
    const int nIter = K >> 5;

    uint32_t sBase = (uint32_t)__cvta_generic_to_shared(dsmem);

    #define LOAD_TILE(it, st) {                                                     \
        uint32_t sa = sBase + (st)*ST_ELE*2;                                        \
        uint32_t sb = sa + A_ELE*2;                                                 \
        int kt = (it) << 5;                                                         \
        _Pragma("unroll")                                                           \
        for (int i = 0; i < 2; i++) {                                               \
            int idx = tid + i * 256;                                                \
            int r = idx >> 2, ch = idx & 3;                                         \
            cpa16(sa + r*80 + ch*16, &A[(size_t)(row0 + r) * K + kt + ch*8]);       \
        }                                                                           \
        _Pragma("unroll")                                                           \
        for (int i = 0; i < 2; i++) {                                               \
            int idx = tid + i * 256;                                                \
            int r = idx >> 2, ch = idx & 3;                                         \
            cpa16(sb + r*80 + ch*16, &W[(size_t)(col0 + r) * K + kt + ch*8]);       \
        }                                                                           \
    }

    float acc[4][4][4] = {};

    LOAD_TILE(0, 0); CP_COMMIT();
    LOAD_TILE(1, 1); CP_COMMIT();

    for (int it = 0; it < nIter; it++) {
        CP_WAIT(1);
        __syncthreads();
        if (it + 2 < nIter) { LOAD_TILE(it + 2, (it + 2) % 3); }
        CP_COMMIT();

        const uint32_t* S32 = (const uint32_t*)(dsmem + (it % 3)*ST_ELE*2);
        const uint32_t* A32 = S32;
        const uint32_t* B32 = S32 + A_ELE/2;
        #pragma unroll
        for (int kk = 0; kk < 2; kk++) {
            int kb2 = kk * 8;
            uint32_t af[4][4], bf[4][2];
            #pragma unroll
            for (int mf = 0; mf < 4; mf++) {
                int r = wm * 64 + mf * 16 + grp;
                af[mf][0] = A32[r * 20 + kb2 + qd];
                af[mf][1] = A32[(r + 8) * 20 + kb2 + qd];
                af[mf][2] = A32[r * 20 + kb2 + qd + 4];
                af[mf][3] = A32[(r + 8) * 20 + kb2 + qd + 4];
            }
            #pragma unroll
            for (int nf = 0; nf < 4; nf++) {
                int c = wn * 32 + nf * 8 + grp;
                bf[nf][0] = B32[c * 20 + kb2 + qd];
                bf[nf][1] = B32[c * 20 + kb2 + qd + 4];
            }
            #pragma unroll
            for (int mf = 0; mf < 4; mf++)
                #pragma unroll
                for (int nf = 0; nf < 4; nf++)
                    mma_f16(acc[mf][nf], af[mf], bf[nf]);
        }
        __syncthreads();
    }
    #undef LOAD_TILE

    #pragma unroll
    for (int mf = 0; mf < 4; mf++) {
        int r = row0 + wm * 64 + mf * 16 + grp;
        #pragma unroll
        for (int nf = 0; nf < 4; nf++) {
            int c = col0 + wn * 32 + nf * 8 + 2 * qd;
            float* a = acc[mf][nf];
            float v0 = a[0], v1 = a[1], v2 = a[2], v3 = a[3];
            if (EPI >= 1) {
                float b0 = bias[c], b1 = bias[c + 1];
                v0 += b0; v1 += b1; v2 += b0; v3 += b1;
            }
            if (EPI == 2) {
                v0 = gelu_tanh_f(v0); v1 = gelu_tanh_f(v1);
                v2 = gelu_tanh_f(v2); v3 = gelu_tanh_f(v3);
            }
            if (EPI == 1) {
                Cf[(size_t)r * N + c] = v0;       Cf[(size_t)r * N + c + 1] = v1;
                Cf[(size_t)(r + 8) * N + c] = v2; Cf[(size_t)(r + 8) * N + c + 1] = v3;
            } else {
                *(__half2*)&Ch[(size_t)r * N + c]       = __floats2half2_rn(v0, v1);
                *(__half2*)&Ch[(size_t)(r + 8) * N + c] = __floats2half2_rn(v2, v3);
            }
        }
    }
}

// =============================================================================
// Fused attention: 256 thr, 32 q-rows per CTA, fp16 Q/K/V AND fp16 score buf.
// smem: sS half[32][1032] (66048B) | Qs half[32][72] | KV half[2][128][72]
//   = 107520 B -> 2 CTAs/SM.
// =============================================================================
#define FA_HS       1032
#define FA_SS_BYTES (32*FA_HS*2)
#define FA_HSTR     72
#define FA_Q_BYTES  (32*FA_HSTR*2)
#define FA_KV_BYTES (128*FA_HSTR*2)
#define FA_SMEM     (FA_SS_BYTES + FA_Q_BYTES + 2*FA_KV_BYTES)

__global__ __launch_bounds__(256, 2)
void fused_attn(const float* __restrict__ attn_bias, const int* __restrict__ mask,
                float* __restrict__ out) {
    __half* sS = (__half*)dsmem;
    char*  qBase  = dsmem + FA_SS_BYTES;
    char*  kvBase = qBase + FA_Q_BYTES;

    const int tid = threadIdx.x;
    const int w = tid >> 5, lane = tid & 31;
    const int wm = w >> 2, wn = w & 3;
    const int grp = lane >> 2, qd = lane & 3;
    const int row0 = blockIdx.x * 32;
    const int z = blockIdx.y, b = z >> 4, h = z & 15;

    const __half* Qg = g_qh + (size_t)b*S_*D_ + h*DK_;
    const __half* Kg = g_kh + (size_t)b*S_*D_ + h*DK_;
    const __half* Vg = g_vh + (size_t)b*S_*D_ + h*DK_;

    uint32_t sQ  = (uint32_t)__cvta_generic_to_shared(qBase);
    uint32_t sKV = (uint32_t)__cvta_generic_to_shared(kvBase);

    // preload Q (32x8 chunks) + K tile 0 (128x8 chunks)
    {
        int r = tid >> 3, ch = tid & 7;
        cpa16(sQ + r*144 + ch*16, &Qg[(size_t)(row0+r)*D_ + ch*8]);
    }
    #pragma unroll
    for (int i = 0; i < 4; i++) {
        int idx = tid + i*256;
        int r = idx >> 3, ch = idx & 7;
        cpa16(sKV + r*144 + ch*16, &Kg[(size_t)r*D_ + ch*8]);
    }
    CP_COMMIT();

    // ---- phase 1: S = scale * Q K^T  (8 key tiles of 128), store fp16 ----
    for (int t = 0; t < 8; t++) {
        __syncthreads();
        if (t + 1 < 8) {
            uint32_t dst = sKV + ((t+1)&1)*FA_KV_BYTES;
            int key0 = (t+1)*128;
            #pragma unroll
            for (int i = 0; i < 4; i++) {
                int idx = tid + i*256;
                int r = idx >> 3, ch = idx & 7;
                cpa16(dst + r*144 + ch*16, &Kg[(size_t)(key0+r)*D_ + ch*8]);
            }
        }
        CP_COMMIT();
        CP_WAIT(1);
        __syncthreads();

        const uint32_t* Q32 = (const uint32_t*)qBase;
        const uint32_t* K32 = (const uint32_t*)(kvBase + (t&1)*FA_KV_BYTES);
        float acc[4][4] = {};
        #pragma unroll
        for (int kk = 0; kk < 4; kk++) {
            int kb2 = kk * 8;
            uint32_t af[4], bf[4][2];
            int r = wm*16 + grp;
            af[0] = Q32[r*36 + kb2 + qd];
            af[1] = Q32[(r+8)*36 + kb2 + qd];
            af[2] = Q32[r*36 + kb2 + qd + 4];
            af[3] = Q32[(r+8)*36 + kb2 + qd + 4];
            #pragma unroll
            for (int nf = 0; nf < 4; nf++) {
                int c = wn*32 + nf*8 + grp;
                bf[nf][0] = K32[c*36 + kb2 + qd];
                bf[nf][1] = K32[c*36 + kb2 + qd + 4];
            }
            #pragma unroll
            for (int nf = 0; nf < 4; nf++)
                mma_f16(acc[nf], af, bf[nf]);
        }
        {
            int r = wm*16 + grp;
            #pragma unroll
            for (int nf = 0; nf < 4; nf++) {
                int c = t*128 + wn*32 + nf*8 + 2*qd;
                *(__half2*)&sS[r*FA_HS + c]     = __floats2half2_rn(acc[nf][0]*0.125f, acc[nf][1]*0.125f);
                *(__half2*)&sS[(r+8)*FA_HS + c] = __floats2half2_rn(acc[nf][2]*0.125f, acc[nf][3]*0.125f);
            }
        }
    }
    __syncthreads();

    // prefetch V tile 0 (overlaps softmax)
    #pragma unroll
    for (int i = 0; i < 4; i++) {
        int idx = tid + i*256;
        int r = idx >> 3, ch = idx & 7;
        cpa16(sKV + r*144 + ch*16, &Vg[(size_t)r*D_ + ch*8]);
    }
    CP_COMMIT();

    // ---- phase 2: softmax, warp per row; p -> fp16 smem + f32 gmem ----
    {
        const float* biasZ = attn_bias + (size_t)z*S_*S_;
        float* outZ = out + (size_t)z*S_*S_;
        const int* maskB = mask + b*S_;
        #pragma unroll
        for (int ri = 0; ri < 4; ri++) {
            int r = w*4 + ri;
            const float* bRow = biasZ + (size_t)(row0+r)*S_;
            float* oRow = outZ + (size_t)(row0+r)*S_;
            __half* sRow = sS + r*FA_HS;
            float4 vals[8];
            float m = -INFINITY;
            #pragma unroll
            for (int j = 0; j < 8; j++) {
                int c = lane*4 + j*128;
                __half2 h01 = *(__half2*)&sRow[c];
                __half2 h23 = *(__half2*)&sRow[c + 2];
                float2 f01 = __half22float2(h01);
                float2 f23 = __half22float2(h23);
                float4 bv = *(const float4*)&bRow[c];
                int4 mk = *(const int4*)&maskB[c];
                float4 v;
                v.x = mk.x ? f01.x + bv.x : -9e15f;
                v.y = mk.y ? f01.y + bv.y : -9e15f;
                v.z = mk.z ? f23.x + bv.z : -9e15f;
                v.w = mk.w ? f23.y + bv.w : -9e15f;
                vals[j] = v;
                m = fmaxf(m, fmaxf(fmaxf(v.x, v.y), fmaxf(v.z, v.w)));
            }
            #pragma unroll
            for (int o = 16; o > 0; o >>= 1) m = fmaxf(m, __shfl_xor_sync(~0u, m, o));
            float sum = 0.f;
            #pragma unroll
            for (int j = 0; j < 8; j++) {
                float4 v = vals[j];
                v.x = __expf(v.x - m); v.y = __expf(v.y - m);
                v.z = __expf(v.z - m); v.w = __expf(v.w - m);
                vals[j] = v;
                sum += v.x + v.y + v.z + v.w;
            }
            #pragma unroll
            for (int o = 16; o > 0; o >>= 1) sum += __shfl_xor_sync(~0u, sum, o);
            float inv = 1.0f / sum;
            #pragma unroll
            for (int j = 0; j < 8; j++) {
                int c = lane*4 + j*128;
                float4 v = vals[j];
                v.x *= inv; v.y *= inv; v.z *= inv; v.w *= inv;
                *(__half2*)&sRow[c]     = __floats2half2_rn(v.x, v.y);
                *(__half2*)&sRow[c + 2] = __floats2half2_rn(v.z, v.w);
                *(float4*)&oRow[c] = v;
            }
        }
    }

    // ---- phase 3: O = P @ V  (8 value tiles of 128); P read as packed fp16 ----
    float accO[2][4] = {};
    for (int t = 0; t < 8; t++) {
        __syncthreads();
        if (t + 1 < 8) {
            uint32_t dst = sKV + ((t+1)&1)*FA_KV_BYTES;
            int key0 = (t+1)*128;
            #pragma unroll
            for (int i = 0; i < 4; i++) {
                int idx = tid + i*256;
                int r = idx >> 3, ch = idx & 7;
                cpa16(dst + r*144 + ch*16, &Vg[(size_t)(key0+r)*D_ + ch*8]);
            }
        }
        CP_COMMIT();
        CP_WAIT(1);
        __syncthreads();

        const __half* Vs = (const __half*)(kvBase + (t&1)*FA_KV_BYTES);
        #pragma unroll
        for (int kk = 0; kk < 8; kk++) {
            int kl = kk * 16;
            int kg = t*128 + kl;
            uint32_t af[4];
            int r = wm*16 + grp;
            af[0] = *(const uint32_t*)&sS[r*FA_HS + kg + 2*qd];
            af[1] = *(const uint32_t*)&sS[(r+8)*FA_HS + kg + 2*qd];
            af[2] = *(const uint32_t*)&sS[r*FA_HS + kg + 2*qd + 8];
            af[3] = *(const uint32_t*)&sS[(r+8)*FA_HS + kg + 2*qd + 8];
            #pragma unroll
            for (int nf = 0; nf < 2; nf++) {
                int c = wn*16 + nf*8 + grp;
                uint32_t bf[2];
                bf[0] = packh2(Vs[(kl + 2*qd)*FA_HSTR + c],     Vs[(kl + 2*qd + 1)*FA_HSTR + c]);
                bf[1] = packh2(Vs[(kl + 2*qd + 8)*FA_HSTR + c], Vs[(kl + 2*qd + 9)*FA_HSTR + c]);
                mma_f16(accO[nf], af, bf);
            }
        }
    }
    {
        float* Og = g_o + (size_t)b*S_*D_ + h*DK_;
        int r = row0 + wm*16 + grp;
        #pragma unroll
        for (int nf = 0; nf < 2; nf++) {
            int c = wn*16 + nf*8 + 2*qd;
            Og[(size_t)r*D_ + c]       = accO[nf][0];
            Og[(size_t)r*D_ + c + 1]   = accO[nf][1];
            Og[(size_t)(r+8)*D_ + c]   = accO[nf][2];
            Og[(size_t)(r+8)*D_ + c+1] = accO[nf][3];
        }
    }
}

// ---------------- x = LayerNorm(x + r) * g + b, shuffle reduction, +fp16 ----
__global__ void add_ln(float* __restrict__ x, const float* __restrict__ r,
                       const float* __restrict__ g, const float* __restrict__ bb,
                       __half* __restrict__ xh) {
    float* row = x + (size_t)blockIdx.x * D_;
    const float* rr = r + (size_t)blockIdx.x * D_;
    __half* hrow = xh + (size_t)blockIdx.x * D_;
    __shared__ float red[8], red2[8];
    int t = threadIdx.x;
    int w = t >> 5, lane = t & 31;
    float v[4];
    float s = 0.f, s2 = 0.f;
    #pragma unroll
    for (int i = 0; i < 4; i++) {
        v[i] = row[t + i * 256] + rr[t + i * 256];
        s += v[i]; s2 += v[i] * v[i];
    }
    #pragma unroll
    for (int o = 16; o > 0; o >>= 1) {
        s  += __shfl_xor_sync(~0u, s, o);
        s2 += __shfl_xor_sync(~0u, s2, o);
    }
    if (lane == 0) { red[w] = s; red2[w] = s2; }
    __syncthreads();
    float ts = 0.f, ts2 = 0.f;
    #pragma unroll
    for (int i = 0; i < 8; i++) { ts += red[i]; ts2 += red2[i]; }
    float mu = ts * (1.0f / D_);
    float var = ts2 * (1.0f / D_) - mu * mu;
    float inv = rsqrtf(var + 1e-6f);
    #pragma unroll
    for (int i = 0; i < 4; i++) {
        int c = t + i * 256;
        float o = (v[i] - mu) * inv * g[c] + bb[c];
        row[c] = o;
        hrow[c] = __float2half(o);
    }
}

// ---------------- weight prep: W[K][N] f32 -> WT[N][K] fp16 -----------------
__global__ void wt_prep(const float* __restrict__ Wq, const float* __restrict__ Wk,
                        const float* __restrict__ Wv, const float* __restrict__ W1,
                        const float* __restrict__ W2) {
    int z = blockIdx.z;
    const float* src; __half* dst; int K, N;
    if (z < 12) {
        int l = z / 3, which = z % 3;
        const float* base = (which == 0) ? Wq : (which == 1) ? Wk : Wv;
        src = base + (size_t)l * D_ * D_;
        dst = g_wqkvh + (size_t)z * D_ * D_;
        K = D_; N = D_;
    } else if (z < 16) {
        int l = z - 12;
        src = W1 + (size_t)l * D_ * DFF_;
        dst = g_w1h + (size_t)l * DFF_ * D_;
        K = D_; N = DFF_;
    } else {
        int l = z - 16;
        src = W2 + (size_t)l * DFF_ * D_;
        dst = g_w2h + (size_t)l * D_ * DFF_;
        K = DFF_; N = D_;
    }
    int n0 = blockIdx.x * 32, k0 = blockIdx.y * 32;
    if (n0 >= N || k0 >= K) return;
    __shared__ float tile[32][33];
    int tid = threadIdx.x;
    #pragma unroll
    for (int i = 0; i < 4; i++) {
        int idx = tid + i * 256;
        int kr = idx >> 5, nc = idx & 31;
        tile[kr][nc] = src[(size_t)(k0 + kr) * N + n0 + nc];
    }
    __syncthreads();
    #pragma unroll
    for (int i = 0; i < 4; i++) {
        int idx = tid + i * 256;
        int nr = idx >> 5, kc = idx & 31;
        dst[(size_t)(n0 + nr) * K + k0 + kc] = __float2half(tile[kc][nr]);
    }
}

// ---------------- helpers ----------------------------------------------------
__global__ void split_copy(float* __restrict__ dst, __half* __restrict__ dsth,
                           const float* __restrict__ src) {
    int i = (blockIdx.x * 256 + threadIdx.x) * 4;
    float4 v = *(const float4*)&src[i];
    *(float4*)&dst[i] = v;
    *(__half2*)&dsth[i]     = __floats2half2_rn(v.x, v.y);
    *(__half2*)&dsth[i + 2] = __floats2half2_rn(v.z, v.w);
}

__global__ void copyk(float* __restrict__ dst, const float* __restrict__ src, int n) {
    int i = blockIdx.x * 256 + threadIdx.x;
    if (i < n) dst[i] = src[i];
}

// ---------------------------------------------------------------------------
extern "C" void kernel_launch(void* const* d_in, const int* in_sizes, int n_in,
                              void* d_out, int out_size) {
    const float* x_in      = (const float*)d_in[0];
    const int*   mask      = (const int*)d_in[1];
    const float* attn_bias = (const float*)d_in[2];
    const float* Wq        = (const float*)d_in[3];
    const float* Wk        = (const float*)d_in[4];
    const float* Wv        = (const float*)d_in[5];
    const float* ln1_g     = (const float*)d_in[6];
    const float* ln1_b     = (const float*)d_in[7];
    const float* W1        = (const float*)d_in[8];
    const float* b1        = (const float*)d_in[9];
    const float* W2        = (const float*)d_in[10];
    const float* b2        = (const float*)d_in[11];
    const float* ln2_g     = (const float*)d_in[12];
    const float* ln2_b     = (const float*)d_in[13];
    float* out = (float*)d_out;

    cudaFuncSetAttribute(gemm_pipe<0>, cudaFuncAttributeMaxDynamicSharedMemorySize, GEMM_SMEM);
    cudaFuncSetAttribute(gemm_pipe<1>, cudaFuncAttributeMaxDynamicSharedMemorySize, GEMM_SMEM);
    cudaFuncSetAttribute(gemm_pipe<2>, cudaFuncAttributeMaxDynamicSharedMemorySize, GEMM_SMEM);
    cudaFuncSetAttribute(fused_attn,   cudaFuncAttributeMaxDynamicSharedMemorySize, FA_SMEM);

    float *px, *po, *pf;
    __half *pxh, *pqh, *pkh, *pvh, *phh, *pwqkvh, *pw1h, *pw2h;
    cudaGetSymbolAddress((void**)&px, g_x);
    cudaGetSymbolAddress((void**)&po, g_o);
    cudaGetSymbolAddress((void**)&pf, g_f);
    cudaGetSymbolAddress((void**)&pxh, g_xh);
    cudaGetSymbolAddress((void**)&pqh, g_qh);
    cudaGetSymbolAddress((void**)&pkh, g_kh);
    cudaGetSymbolAddress((void**)&pvh, g_vh);
    cudaGetSymbolAddress((void**)&phh, g_hh);
    cudaGetSymbolAddress((void**)&pwqkvh, g_wqkvh);
    cudaGetSymbolAddress((void**)&pw1h, g_w1h);
    cudaGetSymbolAddress((void**)&pw2h, g_w2h);

    const int nX = BS_ * D_;

    wt_prep<<<dim3(64, 64, 20), 256>>>(Wq, Wk, Wv, W1, W2);
    split_copy<<<nX / 1024, 256>>>(px, pxh, x_in);

    dim3 gQKV(D_ / 128, BS_ / 128, 3);     // 8 x 16 x 3
    dim3 gFF1(DFF_ / 128, BS_ / 128, 1);   // 16 x 16
    dim3 gFF2(D_ / 128, BS_ / 128, 1);     // 8 x 16
    dim3 gFA(S_ / 32, B_ * H_);            // 32 x 32

    for (int n = 0; n < L_; n++) {
        float* scores = out + (size_t)n * B_ * H_ * S_ * S_;
        const __half* wqkv = pwqkvh + (size_t)n * 3 * D_ * D_;

        gemm_pipe<0><<<gQKV, 256, GEMM_SMEM>>>(
            pxh, wqkv, wqkv + (size_t)D_ * D_, wqkv + (size_t)2 * D_ * D_,
            nullptr, nullptr, pqh, pkh, pvh, D_, D_);

        fused_attn<<<gFA, 256, FA_SMEM>>>(attn_bias, mask, scores);

        add_ln<<<BS_, 256>>>(px, po, ln1_g + n * D_, ln1_b + n * D_, pxh);

        gemm_pipe<2><<<gFF1, 256, GEMM_SMEM>>>(
            pxh, pw1h + (size_t)n * DFF_ * D_, pw1h + (size_t)n * DFF_ * D_,
            pw1h + (size_t)n * DFF_ * D_, b1 + n * DFF_,
            nullptr, phh, phh, phh, DFF_, D_);

        gemm_pipe<1><<<gFF2, 256, GEMM_SMEM>>>(
            phh, pw2h + (size_t)n * D_ * DFF_, pw2h + (size_t)n * D_ * DFF_,
            pw2h + (size_t)n * D_ * DFF_, b2 + n * D_,
            pf, nullptr, nullptr, nullptr, D_, DFF_);

        add_ln<<<BS_, 256>>>(px, pf, ln2_g + n * D_, ln2_b + n * D_, pxh);
    }

    copyk<<<(nX + 255) / 256, 256>>>(out + (size_t)L_ * B_ * H_ * S_ * S_, px, nX);
}